// round 7
// baseline (speedup 1.0000x reference)
#include <cuda_runtime.h>
#include <cuda_bf16.h>
#include <cstdint>

#define NN    50000
#define EE    800000
#define RR    4
#define NRSEG (NN*RR)
#define DD    128
#define NG    128
#define NC    16
#define KK    640
#define MT    128
#define GEMM_BLOCKS ((NN + MT - 1) / MT)   // 391

// fused-kernel smem: A/B tiles of 128 rows x 128 bf16, row pitch 136 bf16 (272B)
#define RPB     272
#define TILE2B  (128 * RPB)                // 34816
#define OFF_AH  0
#define OFF_AL  (TILE2B)
#define OFF_BH  (2 * TILE2B)
#define OFF_BL  (3 * TILE2B)
#define SMEM_TOTAL (4 * TILE2B)            // 139264

// ---------------- scratch (device globals) ----------------------------------
__device__ int   g_cnt[NRSEG];
__device__ int   g_off[NRSEG + 1];
__device__ int   g_cur[NRSEG];
__device__ int   g_srce[EE];
__device__ int   g_sege[EE];
__device__ int   g_srcs[EE];
__device__ __nv_bfloat16 g_B1hi[DD * KK], g_B1lo[DD * KK];   // weights [N=128,K=640]
__device__ __nv_bfloat16 g_B2hi[DD * KK], g_B2lo[DD * KK];
__device__ float g_h1[NN * DD];
__device__ float g_h2[NN * DD];
__device__ int   g_gstart[NG + 1];

// ---------------- helpers ----------------------------------------------------
__device__ __forceinline__ uint32_t smem_u32(const void* p) {
    uint32_t a;
    asm("{ .reg .u64 t; cvta.to.shared.u64 t, %1; cvt.u32.u64 %0, t; }"
        : "=r"(a) : "l"(p));
    return a;
}

__device__ __forceinline__ void cp16(uint32_t dst, const void* src) {
    asm volatile("cp.async.cg.shared.global [%0], [%1], 16;" :: "r"(dst), "l"(src));
}
#define CP_COMMIT() asm volatile("cp.async.commit_group;" ::: "memory")
#define CP_WAIT0()  asm volatile("cp.async.wait_group 0;" ::: "memory")

__device__ __forceinline__ void mma_bf16(float* d, const uint32_t* a,
                                         uint32_t b0, uint32_t b1) {
    asm volatile(
        "mma.sync.aligned.m16n8k16.row.col.f32.bf16.bf16.f32 "
        "{%0,%1,%2,%3}, {%4,%5,%6,%7}, {%8,%9}, {%0,%1,%2,%3};\n"
        : "+f"(d[0]), "+f"(d[1]), "+f"(d[2]), "+f"(d[3])
        : "r"(a[0]), "r"(a[1]), "r"(a[2]), "r"(a[3]), "r"(b0), "r"(b1));
}

__device__ __forceinline__ void split_bf16(float v, __nv_bfloat16& hi, __nv_bfloat16& lo) {
    hi = __float2bfloat16_rn(v);
    lo = __float2bfloat16_rn(v - __bfloat162float(hi));
}

// ---------------- edge preprocessing ----------------------------------------
__global__ void zero_cnt_kernel() {
    int i = blockIdx.x * blockDim.x + threadIdx.x;
    if (i < NRSEG) g_cnt[i] = 0;
}

__global__ void hist_kernel(const int* __restrict__ ei,
                            const int* __restrict__ et) {
    int e = blockIdx.x * blockDim.x + threadIdx.x;
    if (e >= EE) return;
    int src = ei[e];
    int dst = ei[EE + e];
    int ty  = et[e];
    int seg = dst * RR + ty;
    g_srce[e] = src;
    g_sege[e] = seg;
    atomicAdd(&g_cnt[seg], 1);
}

__global__ void scan_kernel() {
    __shared__ int sh[1024];
    int t = threadIdx.x;
    const int C = (NRSEG + 1023) / 1024;
    int b = t * C;
    int e = min(b + C, NRSEG);
    int s = 0;
    for (int i = b; i < e; i++) s += g_cnt[i];
    sh[t] = s;
    __syncthreads();
    for (int d = 1; d < 1024; d <<= 1) {
        int v = (t >= d) ? sh[t - d] : 0;
        __syncthreads();
        sh[t] += v;
        __syncthreads();
    }
    int excl = sh[t] - s;
    if (t == 1023) g_off[NRSEG] = sh[1023];
    int a = excl;
    for (int i = b; i < e; i++) {
        g_off[i] = a;
        g_cur[i] = a;
        a += g_cnt[i];
    }
}

__global__ void scatter_kernel() {
    int e = blockIdx.x * blockDim.x + threadIdx.x;
    if (e >= EE) return;
    int seg = g_sege[e];
    int pos = atomicAdd(&g_cur[seg], 1);
    g_srcs[pos] = g_srce[e];
}

// ---------------- weight conversion ------------------------------------------
// weights -> [N=128 rows (f), K=640 cols] bf16 hi/lo (transposed)
__global__ void convw_kernel(const float* __restrict__ Wrel1,
                             const float* __restrict__ Wroot1,
                             const float* __restrict__ Wrel2,
                             const float* __restrict__ Wroot2) {
    int i = blockIdx.x * blockDim.x + threadIdx.x;
    if (i >= 2 * DD * KK) return;
    int layer = i / (DD * KK);
    int rem   = i % (DD * KK);
    int f = rem / KK;
    int k = rem % KK;
    const float* Wr = layer ? Wrel2 : Wrel1;
    const float* Wo = layer ? Wroot2 : Wroot1;
    float v = (k < 512) ? Wr[k * DD + f] : Wo[(k - 512) * DD + f];
    __nv_bfloat16 hi, lo;
    split_bf16(v, hi, lo);
    if (layer) { g_B2hi[rem] = hi; g_B2lo[rem] = lo; }
    else       { g_B1hi[rem] = hi; g_B1lo[rem] = lo; }
}

// ---------------- fused agg + HMMA GEMM --------------------------------------
// out = relu([mean_r(x[src]) for r | x] @ [Wrel;Wroot]^T + bias)
// 5 k-blocks of 128: relations 0..3 aggregated on the fly, block 4 = residual.
template<int LAYER>
__global__ void __launch_bounds__(512)
fused_gemm_kernel(const float4* __restrict__ Xin,  // layer-0 input (x)
                  const float* __restrict__ bias) {
    const float4* S4 = (LAYER == 0) ? Xin : (const float4*)g_h1;  // device-side bind
    extern __shared__ char smem[];
    const uint32_t sb = smem_u32(smem);
    const int tid  = threadIdx.x;
    const int lane = tid & 31, wid = tid >> 5;
    const int wm = wid & 3, wn = wid >> 2;            // 4x4 warp grid, 32x32 tiles
    const int m0 = blockIdx.x * MT;

    const __nv_bfloat16* Bh = (LAYER == 0) ? g_B1hi : g_B2hi;
    const __nv_bfloat16* Bl = (LAYER == 0) ? g_B1lo : g_B2lo;
    float* Hout = (LAYER == 0) ? g_h1 : g_h2;

    float acc[2][4][4];
#pragma unroll
    for (int f = 0; f < 2; f++)
#pragma unroll
        for (int j = 0; j < 4; j++)
#pragma unroll
            for (int q = 0; q < 4; q++) acc[f][j][q] = 0.f;

    for (int s = 0; s < 5; s++) {
        // ---- prefetch B k-block (hi+lo) via cp.async --------------------
        {
#pragma unroll
            for (int i = 0; i < 8; i++) {
                int idx  = i * 512 + tid;            // 0..4095
                int part = idx >> 11;                // 0=hi, 1=lo
                int rem  = idx & 2047;
                int row  = rem >> 4;
                int ch   = rem & 15;
                uint32_t dst = sb + (part ? OFF_BL : OFF_BH) + row * RPB + ch * 16;
                const __nv_bfloat16* src =
                    (part ? Bl : Bh) + (size_t)row * KK + s * 128 + ch * 8;
                cp16(dst, src);
            }
            CP_COMMIT();
        }
        // ---- aggregate A k-block into smem (warp = row, 8 rows each) ----
        {
            char* AHp = smem + OFF_AH;
            char* ALp = smem + OFF_AL;
#pragma unroll 1
            for (int i = 0; i < 8; i++) {
                int row = wid + i * 16;
                int gm  = m0 + row;
                float4 a4 = make_float4(0.f, 0.f, 0.f, 0.f);
                if (gm < NN) {
                    if (s < 4) {
                        int seg = gm * RR + s;
                        int o0 = g_off[seg], o1 = g_off[seg + 1];
                        for (int e = o0; e < o1; e++) {
                            int src = g_srcs[e];
                            float4 v = S4[src * 32 + lane];
                            a4.x += v.x; a4.y += v.y; a4.z += v.z; a4.w += v.w;
                        }
                        float norm = (o1 > o0) ? 1.f / (float)(o1 - o0) : 0.f;
                        a4.x *= norm; a4.y *= norm; a4.z *= norm; a4.w *= norm;
                    } else {
                        a4 = S4[gm * 32 + lane];     // residual (root) input
                    }
                }
                union { __nv_bfloat16 h[4]; uint2 u; } hh, ll;
                split_bf16(a4.x, hh.h[0], ll.h[0]);
                split_bf16(a4.y, hh.h[1], ll.h[1]);
                split_bf16(a4.z, hh.h[2], ll.h[2]);
                split_bf16(a4.w, hh.h[3], ll.h[3]);
                *(uint2*)(AHp + row * RPB + lane * 8) = hh.u;
                *(uint2*)(ALp + row * RPB + lane * 8) = ll.u;
            }
        }
        CP_WAIT0();
        __syncthreads();
        // ---- MMA over this 128-k block ----------------------------------
        {
            const char* AH = smem + OFF_AH;
            const char* AL = smem + OFF_AL;
            const char* BH = smem + OFF_BH;
            const char* BL = smem + OFF_BL;
#pragma unroll
            for (int ks = 0; ks < 8; ks++) {
                int kb = ks * 32 + (lane & 3) * 4;   // byte offset within row
                uint32_t ah[2][4], al[2][4];
#pragma unroll
                for (int f = 0; f < 2; f++) {
                    int r = wm * 32 + f * 16 + (lane >> 2);
                    const char* pa = AH + r * RPB + kb;
                    ah[f][0] = *(const uint32_t*)(pa);
                    ah[f][1] = *(const uint32_t*)(pa + 8 * RPB);
                    ah[f][2] = *(const uint32_t*)(pa + 16);
                    ah[f][3] = *(const uint32_t*)(pa + 8 * RPB + 16);
                    const char* pl = AL + r * RPB + kb;
                    al[f][0] = *(const uint32_t*)(pl);
                    al[f][1] = *(const uint32_t*)(pl + 8 * RPB);
                    al[f][2] = *(const uint32_t*)(pl + 16);
                    al[f][3] = *(const uint32_t*)(pl + 8 * RPB + 16);
                }
#pragma unroll
                for (int j = 0; j < 4; j++) {
                    int n = wn * 32 + j * 8 + (lane >> 2);
                    const char* pb = BH + n * RPB + kb;
                    uint32_t bh0 = *(const uint32_t*)(pb);
                    uint32_t bh1 = *(const uint32_t*)(pb + 16);
                    const char* pc = BL + n * RPB + kb;
                    uint32_t bl0 = *(const uint32_t*)(pc);
                    uint32_t bl1 = *(const uint32_t*)(pc + 16);
#pragma unroll
                    for (int f = 0; f < 2; f++) {
                        mma_bf16(acc[f][j], ah[f], bh0, bh1);
                        mma_bf16(acc[f][j], ah[f], bl0, bl1);
                        mma_bf16(acc[f][j], al[f], bh0, bh1);
                    }
                }
            }
        }
        __syncthreads();
    }

    // ---- epilogue: bias + relu -> fp32 -------------------------------------
#pragma unroll
    for (int f = 0; f < 2; f++) {
#pragma unroll
        for (int j = 0; j < 4; j++) {
            int c = wn * 32 + j * 8 + (lane & 3) * 2;
            float b0 = bias[c], b1 = bias[c + 1];
#pragma unroll
            for (int h = 0; h < 2; h++) {
                int gm = m0 + wm * 32 + f * 16 + (lane >> 2) + h * 8;
                if (gm >= NN) continue;
                float v0 = fmaxf(acc[f][j][h * 2 + 0] + b0, 0.f);
                float v1 = fmaxf(acc[f][j][h * 2 + 1] + b1, 0.f);
                *(float2*)(Hout + (size_t)gm * DD + c) = make_float2(v0, v1);
            }
        }
    }
}

// ---------------- graph boundaries ------------------------------------------
__global__ void bounds_kernel(const int* __restrict__ batch) {
    int n = blockIdx.x * blockDim.x + threadIdx.x;
    if (n >= NN) return;
    int b  = batch[n];
    int bp = (n == 0) ? -1 : batch[n - 1];
    for (int g = bp + 1; g <= b; g++) g_gstart[g] = n;
    if (n == NN - 1)
        for (int g = b + 1; g <= NG; g++) g_gstart[g] = NN;
}

// ---------------- mean pool + classifier ------------------------------------
__global__ void __launch_bounds__(512)
poolcls_kernel(const float* __restrict__ Wcls,
               const float* __restrict__ bcls,
               float* __restrict__ out) {
    __shared__ float part[4][DD];
    __shared__ float mean[DD];
    int g   = blockIdx.x;
    int tid = threadIdx.x;
    int sub = tid >> 7, d = tid & 127;
    int n0 = g_gstart[g], n1 = g_gstart[g + 1];
    float s = 0.f;
    for (int n = n0 + sub; n < n1; n += 4) s += g_h2[(size_t)n * DD + d];
    part[sub][d] = s;
    __syncthreads();
    if (sub == 0) {
        float c = (float)(n1 - n0);
        mean[d] = (part[0][d] + part[1][d] + part[2][d] + part[3][d]) /
                  fmaxf(c, 1.f);
    }
    __syncthreads();
    if (tid < NC) {
        float a = bcls[tid];
        for (int k = 0; k < DD; k++) a += mean[k] * Wcls[k * NC + tid];
        out[g * NC + tid] = a;
    }
}

// ---------------- launch -----------------------------------------------------
extern "C" void kernel_launch(void* const* d_in, const int* in_sizes, int n_in,
                              void* d_out, int out_size) {
    const float* x      = (const float*)d_in[0];
    const int*   ei     = (const int*)d_in[1];
    const int*   et     = (const int*)d_in[2];
    const int*   batch  = (const int*)d_in[3];
    const float* Wrel1  = (const float*)d_in[4];
    const float* Wroot1 = (const float*)d_in[5];
    const float* b1     = (const float*)d_in[6];
    const float* Wrel2  = (const float*)d_in[7];
    const float* Wroot2 = (const float*)d_in[8];
    const float* b2     = (const float*)d_in[9];
    const float* Wcls   = (const float*)d_in[10];
    const float* bcls   = (const float*)d_in[11];
    float*       out    = (float*)d_out;

    cudaFuncSetAttribute(fused_gemm_kernel<0>,
                         cudaFuncAttributeMaxDynamicSharedMemorySize, SMEM_TOTAL);
    cudaFuncSetAttribute(fused_gemm_kernel<1>,
                         cudaFuncAttributeMaxDynamicSharedMemorySize, SMEM_TOTAL);

    const int TB = 256;
    // edge CSR (once; reused by both layers)
    zero_cnt_kernel<<<(NRSEG + TB - 1) / TB, TB>>>();
    hist_kernel<<<(EE + TB - 1) / TB, TB>>>(ei, et);
    scan_kernel<<<1, 1024>>>();
    scatter_kernel<<<(EE + TB - 1) / TB, TB>>>();

    // weight bf16 splits (transposed)
    convw_kernel<<<(2 * DD * KK + TB - 1) / TB, TB>>>(Wrel1, Wroot1, Wrel2, Wroot2);

    // fused layers (layer-2 source bound inside device code via LAYER)
    fused_gemm_kernel<0><<<GEMM_BLOCKS, 512, SMEM_TOTAL>>>((const float4*)x, b1);
    fused_gemm_kernel<1><<<GEMM_BLOCKS, 512, SMEM_TOTAL>>>(nullptr, b2);

    // pool + classify
    bounds_kernel<<<(NN + TB - 1) / TB, TB>>>(batch);
    poolcls_kernel<<<NG, 512>>>(Wcls, bcls, out);
}